// round 3
// baseline (speedup 1.0000x reference)
#include <cuda_runtime.h>
#include <cstdint>

// Problem constants
#define TT 512
#define BB 64
#define DD 1024
#define HH 1024
#define NBLK 128          // recurrence CTAs; each owns 8 H-cols x 4 gates = 32 output cols
#define CPB 8             // H-columns per gate per block
#define COLS 32           // 4*CPB

// Scratch (device globals: allocation-free per harness rules)
__device__ float g_XG[(size_t)TT * NBLK * BB * COLS];   // 512 MB: x-projection, [t][bk][row][c]
__device__ float g_Whp[(size_t)NBLK * HH * COLS];       // 16 MB: packed recurrent weights [bk][k][c]
__device__ float g_H[2][BB * HH];                       // double-buffered hidden state
__device__ unsigned g_bar;                              // grid barrier counter

// ---------------------------------------------------------------------------
// Init: H(0) = H0, reset barrier
__global__ void init_kernel(const float* __restrict__ H0) {
    int i = blockIdx.x * blockDim.x + threadIdx.x;
    if (i < BB * HH) g_H[0][i] = H0[i];
    if (i == 0) g_bar = 0u;
}

// ---------------------------------------------------------------------------
// Pack recurrent weights: g_Whp[bk][k][c] = W_hg[k][bk*8 + (c&7)], g = c>>3
__global__ void pack_wh_kernel(const float* __restrict__ Wi, const float* __restrict__ Wf,
                               const float* __restrict__ Wo, const float* __restrict__ Wc) {
    int idx = blockIdx.x * 1024 + threadIdx.x;          // over NBLK*HH*COLS = 4M
    int bk  = idx >> 15;
    int rem = idx & 32767;
    int k   = rem >> 5;
    int c   = rem & 31;
    int g   = c >> 3;
    int h   = bk * CPB + (c & 7);
    const float* W = (g == 0) ? Wi : (g == 1) ? Wf : (g == 2) ? Wo : Wc;
    g_Whp[idx] = W[k * HH + h];
}

// ---------------------------------------------------------------------------
// Phase 1: XG = X @ W_xg + b_g for all t,b.  M=32768, N=1024 per gate, K=1024.
// Tile 64x64, 256 threads, 4x4 micro-tile, K-chunk 16.
__global__ __launch_bounds__(256)
void xgemm_kernel(const float* __restrict__ X,
                  const float* __restrict__ Wi, const float* __restrict__ Wf,
                  const float* __restrict__ Wo, const float* __restrict__ Wc,
                  const float* __restrict__ bi, const float* __restrict__ bf,
                  const float* __restrict__ bo, const float* __restrict__ bc) {
    __shared__ float As[16][64];   // [k][m]  (transposed on store)
    __shared__ float Bs[16][64];   // [k][n]

    const int gz = blockIdx.z;
    const float* W  = (gz == 0) ? Wi : (gz == 1) ? Wf : (gz == 2) ? Wo : Wc;
    const float* bb = (gz == 0) ? bi : (gz == 1) ? bf : (gz == 2) ? bo : bc;

    const int m0 = blockIdx.y * 64;          // m0 = t*64 exactly (B=64)
    const int n0 = blockIdx.x * 64;
    const int tid = threadIdx.x;
    const int tx = tid & 15, ty = tid >> 4;

    const int lrow = tid >> 2, lkq = tid & 3;    // A-load mapping
    const int lk   = tid >> 4, lnq = tid & 15;   // B-load mapping

    float acc[4][4] = {};

    for (int k0 = 0; k0 < DD; k0 += 16) {
        __syncthreads();
        float4 av = *(const float4*)&X[(size_t)(m0 + lrow) * DD + k0 + lkq * 4];
        As[lkq * 4 + 0][lrow] = av.x;
        As[lkq * 4 + 1][lrow] = av.y;
        As[lkq * 4 + 2][lrow] = av.z;
        As[lkq * 4 + 3][lrow] = av.w;
        *(float4*)&Bs[lk][lnq * 4] =
            *(const float4*)&W[(size_t)(k0 + lk) * HH + n0 + lnq * 4];
        __syncthreads();
#pragma unroll
        for (int kk = 0; kk < 16; ++kk) {
            float4 a = *(float4*)&As[kk][ty * 4];
            float4 b = *(float4*)&Bs[kk][tx * 4];
            acc[0][0] += a.x * b.x; acc[0][1] += a.x * b.y; acc[0][2] += a.x * b.z; acc[0][3] += a.x * b.w;
            acc[1][0] += a.y * b.x; acc[1][1] += a.y * b.y; acc[1][2] += a.y * b.z; acc[1][3] += a.y * b.w;
            acc[2][0] += a.z * b.x; acc[2][1] += a.z * b.y; acc[2][2] += a.z * b.z; acc[2][3] += a.z * b.w;
            acc[3][0] += a.w * b.x; acc[3][1] += a.w * b.y; acc[3][2] += a.w * b.z; acc[3][3] += a.w * b.w;
        }
    }

    const int t = blockIdx.y;   // rows of this tile are batch 0..63 of timestep t
#pragma unroll
    for (int i = 0; i < 4; ++i) {
        const int row = ty * 4 + i;    // batch index
#pragma unroll
        for (int j = 0; j < 4; ++j) {
            const int n  = n0 + tx * 4 + j;
            const int bk = n >> 3;
            const int c  = gz * CPB + (n & 7);
            g_XG[(((size_t)t * NBLK + bk) * BB + row) * COLS + c] = acc[i][j] + bb[n];
        }
    }
}

// ---------------------------------------------------------------------------
// Phase 2: persistent recurrence. 128 CTAs x 256 threads, one grid barrier/step.
__global__ __launch_bounds__(256)
void rec_kernel(const float* __restrict__ C0, float* __restrict__ out, int out_size) {
    __shared__ float As[64][64];   // H chunk, [k][row]
    __shared__ float Ws[64][32];   // recurrent weight chunk, [k][c]
    __shared__ float Gt[64][32];   // gates [row][c]
    __shared__ float Cs[64][CPB];  // cell state slice (persistent across steps)

    const int bk  = blockIdx.x;
    const int tid = threadIdx.x;
    const int tc  = tid & 7;       // 8 col-groups of 4
    const int tr  = tid >> 3;      // 0..31 (rows tr and tr+32)

    // load C0 slice
    for (int p = tid; p < BB * CPB; p += 256) {
        int row = p >> 3, hc = p & 7;
        Cs[row][hc] = C0[row * HH + bk * CPB + hc];
    }

    const float* Wp = g_Whp + (size_t)bk * HH * COLS;

    for (int t = 0; t < TT; ++t) {
        const float* Hin  = g_H[t & 1];
        float*       Hout = g_H[(t + 1) & 1];

        float acc[2][4] = {};

        for (int k0 = 0; k0 < HH; k0 += 64) {
            __syncthreads();
            // stage H chunk (transpose): 64 rows x 64 k
            for (int i = tid; i < 64 * 16; i += 256) {
                int row = i >> 4, q = i & 15;
                float4 v = *(const float4*)&Hin[row * HH + k0 + q * 4];
                As[q * 4 + 0][row] = v.x;
                As[q * 4 + 1][row] = v.y;
                As[q * 4 + 2][row] = v.z;
                As[q * 4 + 3][row] = v.w;
            }
            // stage packed weights: contiguous 64x32
            const float4* src = (const float4*)(Wp + (size_t)k0 * COLS);
            for (int i = tid; i < 64 * 32 / 4; i += 256)
                ((float4*)Ws)[i] = src[i];
            __syncthreads();
#pragma unroll
            for (int kk = 0; kk < 64; ++kk) {
                float a0 = As[kk][tr];
                float a1 = As[kk][tr + 32];
                float4 b = *(float4*)&Ws[kk][tc * 4];
                acc[0][0] += a0 * b.x; acc[0][1] += a0 * b.y; acc[0][2] += a0 * b.z; acc[0][3] += a0 * b.w;
                acc[1][0] += a1 * b.x; acc[1][1] += a1 * b.y; acc[1][2] += a1 * b.z; acc[1][3] += a1 * b.w;
            }
        }

        // add x-projection, stage gates
        const float* xg = g_XG + ((size_t)t * NBLK + bk) * BB * COLS;
        __syncthreads();
#pragma unroll
        for (int i = 0; i < 2; ++i) {
            const int row = tr + i * 32;
#pragma unroll
            for (int j = 0; j < 4; ++j) {
                const int c = tc * 4 + j;
                Gt[row][c] = acc[i][j] + xg[row * COLS + c];
            }
        }
        __syncthreads();

        // fused pointwise LSTM cell
        for (int p = tid; p < BB * CPB; p += 256) {
            const int row = p >> 3, hc = p & 7;
            const float iv = Gt[row][hc];
            const float fv = Gt[row][CPB + hc];
            const float ov = Gt[row][2 * CPB + hc];
            const float gv = Gt[row][3 * CPB + hc];
            const float I = 1.f / (1.f + __expf(-iv));
            const float F = 1.f / (1.f + __expf(-fv));
            const float O = 1.f / (1.f + __expf(-ov));
            const float Cn = F * Cs[row][hc] + I * tanhf(gv);
            const float Hn = O * tanhf(Cn);
            Cs[row][hc] = Cn;
            const int col = bk * CPB + hc;
            Hout[row * HH + col] = Hn;
            out[((size_t)t * BB + row) * HH + col] = Hn;
        }

        // grid barrier (monotonic counter; all 128 CTAs co-resident: 128 <= 148 SMs)
        __syncthreads();
        if (tid == 0) {
            __threadfence();
            atomicAdd(&g_bar, 1u);
            const unsigned target = (unsigned)(t + 1) * NBLK;
            while (*((volatile unsigned*)&g_bar) < target) { }
            __threadfence();
        }
        __syncthreads();
    }

    // finals (H_f, C_f) if the output buffer includes them
    if (out_size >= TT * BB * HH + 2 * BB * HH) {
        float* Hf = out + (size_t)TT * BB * HH;
        float* Cf = Hf + BB * HH;
        const float* Hlast = g_H[TT & 1];
        for (int p = tid; p < BB * CPB; p += 256) {
            const int row = p >> 3, hc = p & 7;
            const int col = bk * CPB + hc;
            Hf[row * HH + col] = Hlast[row * HH + col];
            Cf[row * HH + col] = Cs[row][hc];
        }
    }
}

// ---------------------------------------------------------------------------
extern "C" void kernel_launch(void* const* d_in, const int* in_sizes, int n_in,
                              void* d_out, int out_size) {
    const float* inputs = (const float*)d_in[0];
    const float* H0     = (const float*)d_in[1];
    const float* C0     = (const float*)d_in[2];
    const float* W_xi   = (const float*)d_in[3];
    const float* W_xf   = (const float*)d_in[4];
    const float* W_xo   = (const float*)d_in[5];
    const float* W_xc   = (const float*)d_in[6];
    const float* W_hi   = (const float*)d_in[7];
    const float* W_hf   = (const float*)d_in[8];
    const float* W_ho   = (const float*)d_in[9];
    const float* W_hc   = (const float*)d_in[10];
    const float* b_i    = (const float*)d_in[11];
    const float* b_f    = (const float*)d_in[12];
    const float* b_o    = (const float*)d_in[13];
    const float* b_c    = (const float*)d_in[14];
    float* out = (float*)d_out;

    init_kernel<<<64, 1024>>>(H0);
    pack_wh_kernel<<<(NBLK * HH * COLS) / 1024, 1024>>>(W_hi, W_hf, W_ho, W_hc);

    dim3 ggrid(HH / 64, (TT * BB) / 64, 4);   // (16, 512, 4)
    xgemm_kernel<<<ggrid, 256>>>(inputs, W_xi, W_xf, W_xo, W_xc, b_i, b_f, b_o, b_c);

    rec_kernel<<<NBLK, 256>>>(C0, out, out_size);
}

// round 6
// speedup vs baseline: 1.5157x; 1.5157x over previous
#include <cuda_runtime.h>
#include <cstdint>

// Problem constants
#define TT 512
#define BB 64
#define DD 1024
#define HH 1024
#define NBLK 128          // recurrence CTAs; each owns 8 H-cols x 4 gates = 32 packed cols
#define CPB 8
#define COLS 32

// Device scratch (allocation-free per harness rules)
__device__ float g_XG[(size_t)TT * NBLK * BB * COLS];     // 512 MB x-projection, [t][bk][row][c]
__device__ float g_Whp_hi[(size_t)NBLK * HH * COLS];      // packed recurrent weights, tf32-hi
__device__ float g_Whp_lo[(size_t)NBLK * HH * COLS];      // tf32-lo
__device__ float g_Hhi[BB * HH];                          // hidden state, tf32-split
__device__ float g_Hlo[BB * HH];
__device__ unsigned g_bar;

// ---------------------------------------------------------------------------
__device__ __forceinline__ float tf32_rd(float x) {
    unsigned r;
    asm("cvt.rna.tf32.f32 %0, %1;" : "=r"(r) : "f"(x));
    return __uint_as_float(r);
}

__device__ __forceinline__ void mma8(float* c,
                                     float a0, float a1, float a2, float a3,
                                     float b0, float b1) {
    asm volatile(
        "mma.sync.aligned.m16n8k8.row.col.f32.tf32.tf32.f32 "
        "{%0,%1,%2,%3},{%4,%5,%6,%7},{%8,%9},{%0,%1,%2,%3};"
        : "+f"(c[0]), "+f"(c[1]), "+f"(c[2]), "+f"(c[3])
        : "r"(__float_as_uint(a0)), "r"(__float_as_uint(a1)),
          "r"(__float_as_uint(a2)), "r"(__float_as_uint(a3)),
          "r"(__float_as_uint(b0)), "r"(__float_as_uint(b1)));
}

// ---------------------------------------------------------------------------
// Init: split H0 into tf32 hi/lo, reset barrier
__global__ void init_kernel(const float* __restrict__ H0) {
    int i = blockIdx.x * blockDim.x + threadIdx.x;
    if (i < BB * HH) {
        float h  = H0[i];
        float hi = tf32_rd(h);
        g_Hhi[i] = hi;
        g_Hlo[i] = tf32_rd(h - hi);
    }
    if (i == 0) g_bar = 0u;
}

// ---------------------------------------------------------------------------
// Pack recurrent weights into [bk][k][c] layout, tf32-split.
__global__ void pack_wh_kernel(const float* __restrict__ Wi, const float* __restrict__ Wf,
                               const float* __restrict__ Wo, const float* __restrict__ Wc) {
    int idx = blockIdx.x * 1024 + threadIdx.x;          // over NBLK*HH*COLS = 4M
    int bk  = idx >> 15;
    int rem = idx & 32767;
    int k   = rem >> 5;
    int c   = rem & 31;
    int gt  = c >> 3;
    int h   = bk * CPB + (c & 7);
    const float* W = (gt == 0) ? Wi : (gt == 1) ? Wf : (gt == 2) ? Wo : Wc;
    float w  = W[k * HH + h];
    float hi = tf32_rd(w);
    g_Whp_hi[idx] = hi;
    g_Whp_lo[idx] = tf32_rd(w - hi);
}

// ---------------------------------------------------------------------------
// Phase 1: XG = X @ Wx + b via 3xTF32 mma. CTA tile M=64 (one t), N=128, K=1024.
// Warps 0-3 consume (each m16 x n128), warps 4-7 produce (global->smem + split).
#define XKC 32
#define XSA 36        // A smem row stride (floats), (4g+t4)%32 distinct
#define XSB 132       // B smem row stride
#define XBUF 13056    // per-buffer floats: Ahi 2304 + Alo 2304 + Bhi 4224 + Blo 4224

__global__ __launch_bounds__(256, 2)
void xgemm3_kernel(const float* __restrict__ X,
                   const float* __restrict__ Wi, const float* __restrict__ Wf,
                   const float* __restrict__ Wo, const float* __restrict__ Wc,
                   const float* __restrict__ bi, const float* __restrict__ bf,
                   const float* __restrict__ bo, const float* __restrict__ bc) {
    extern __shared__ float sm[];

    const int t   = blockIdx.y;
    const int n0  = blockIdx.x * 128;
    const int gz  = n0 >> 10;            // gate (128 | 1024 so CTA within one gate)
    const int nc0 = n0 & 1023;           // col offset within gate
    const float* W  = (gz == 0) ? Wi : (gz == 1) ? Wf : (gz == 2) ? Wo : Wc;
    const float* bb = (gz == 0) ? bi : (gz == 1) ? bf : (gz == 2) ? bo : bc;
    const float* Xb = X + (size_t)t * BB * DD;

    const int tid  = threadIdx.x;
    const int wid  = tid >> 5;
    const int lane = tid & 31;
    const int g    = lane >> 2;
    const int t4   = lane & 3;

    float acc[16][4];
#pragma unroll
    for (int i = 0; i < 16; ++i)
#pragma unroll
        for (int j = 0; j < 4; ++j) acc[i][j] = 0.f;

    // ---- producer fill of chunk k0 into buffer s
    auto fill = [&](int s, int k0) {
        float* Ah = sm + s * XBUF;
        float* Al = Ah + 2304;
        float* Bh = Al + 2304;
        float* Bl = Bh + 4224;
        const int p = tid - 128;
        for (int i = p; i < 512; i += 128) {            // X: 64 rows x 8 float4
            int row = i >> 3, q = i & 7;
            float4 v = *(const float4*)&Xb[(size_t)row * DD + k0 + q * 4];
            float4 h, l;
            h.x = tf32_rd(v.x); l.x = tf32_rd(v.x - h.x);
            h.y = tf32_rd(v.y); l.y = tf32_rd(v.y - h.y);
            h.z = tf32_rd(v.z); l.z = tf32_rd(v.z - h.z);
            h.w = tf32_rd(v.w); l.w = tf32_rd(v.w - h.w);
            *(float4*)&Ah[row * XSA + q * 4] = h;
            *(float4*)&Al[row * XSA + q * 4] = l;
        }
        for (int i = p; i < 1024; i += 128) {           // W: 32 rows x 32 float4
            int row = i >> 5, q = i & 31;
            float4 v = *(const float4*)&W[(size_t)(k0 + row) * HH + nc0 + q * 4];
            float4 h, l;
            h.x = tf32_rd(v.x); l.x = tf32_rd(v.x - h.x);
            h.y = tf32_rd(v.y); l.y = tf32_rd(v.y - h.y);
            h.z = tf32_rd(v.z); l.z = tf32_rd(v.z - h.z);
            h.w = tf32_rd(v.w); l.w = tf32_rd(v.w - h.w);
            *(float4*)&Bh[row * XSB + q * 4] = h;
            *(float4*)&Bl[row * XSB + q * 4] = l;
        }
    };

    // ---- consumer compute on buffer s
    auto compute = [&](int s) {
        const float* Ah = sm + s * XBUF;
        const float* Al = Ah + 2304;
        const float* Bh = Al + 2304;
        const float* Bl = Bh + 4224;
        const int r0 = wid * 16 + g;
#pragma unroll
        for (int kk8 = 0; kk8 < 4; ++kk8) {
            const int k = kk8 * 8;
            float ah0 = Ah[r0 * XSA + k + t4];
            float ah1 = Ah[(r0 + 8) * XSA + k + t4];
            float ah2 = Ah[r0 * XSA + k + t4 + 4];
            float ah3 = Ah[(r0 + 8) * XSA + k + t4 + 4];
            float al0 = Al[r0 * XSA + k + t4];
            float al1 = Al[(r0 + 8) * XSA + k + t4];
            float al2 = Al[r0 * XSA + k + t4 + 4];
            float al3 = Al[(r0 + 8) * XSA + k + t4 + 4];
#pragma unroll
            for (int nt = 0; nt < 16; ++nt) {
                float bh0 = Bh[(k + t4) * XSB + nt * 8 + g];
                float bh1 = Bh[(k + t4 + 4) * XSB + nt * 8 + g];
                float bl0 = Bl[(k + t4) * XSB + nt * 8 + g];
                float bl1 = Bl[(k + t4 + 4) * XSB + nt * 8 + g];
                mma8(acc[nt], ah0, ah1, ah2, ah3, bh0, bh1);
                mma8(acc[nt], ah0, ah1, ah2, ah3, bl0, bl1);
                mma8(acc[nt], al0, al1, al2, al3, bh0, bh1);
            }
        }
    };

    if (wid >= 4) fill(0, 0);
    __syncthreads();
    for (int c = 0; c < DD / XKC; ++c) {
        if (wid >= 4) {
            if (c + 1 < DD / XKC) fill((c + 1) & 1, (c + 1) * XKC);
        } else {
            compute(c & 1);
        }
        __syncthreads();
    }

    // Epilogue: add bias, remap to packed [t][bk][row][c] layout
    if (wid < 4) {
        const int r0 = wid * 16 + g;
#pragma unroll
        for (int nt = 0; nt < 16; ++nt) {
            const int nc = nc0 + nt * 8 + 2 * t4;       // col within gate, even
            const int bkk = nc >> 3;
            const int cc  = gz * 8 + (nc & 7);
            const float b0v = bb[nc], b1v = bb[nc + 1];
#pragma unroll
            for (int j = 0; j < 2; ++j) {
                const int row = r0 + 8 * j;
                float2 v;
                v.x = acc[nt][2 * j]     + b0v;
                v.y = acc[nt][2 * j + 1] + b1v;
                *(float2*)&g_XG[(((size_t)t * NBLK + bkk) * BB + row) * COLS + cc] = v;
            }
        }
    }
}

// ---------------------------------------------------------------------------
// Phase 2: persistent recurrence. 128 CTAs x 256 threads, grid barrier/step.
// Warps 0-3 consume (m16 x all 32 cols via 4 n-tiles, 3xTF32 mma); warps 4-7
// stage Hhi/Hlo + W chunks (pure float4 copies, padded strides).
#define RKC 64
#define RSA 68
#define RSB 36
#define RBUF 13312    // Ahi 4352 + Alo 4352 + Bhi 2304 + Blo 2304

__global__ __launch_bounds__(256, 1)
void rec3_kernel(const float* __restrict__ C0, float* __restrict__ out, int out_size) {
    extern __shared__ float sm[];
    float* Cs = sm + 2 * RBUF;          // [64][8] cell state, persistent

    const int bk   = blockIdx.x;
    const int tid  = threadIdx.x;
    const int wid  = tid >> 5;
    const int lane = tid & 31;
    const int g    = lane >> 2;
    const int t4   = lane & 3;

    for (int p = tid; p < BB * CPB; p += 256) {
        int row = p >> 3, h = p & 7;
        Cs[row * 8 + h] = C0[row * HH + bk * CPB + h];
    }

    const float* Wh = g_Whp_hi + (size_t)bk * HH * COLS;
    const float* Wl = g_Whp_lo + (size_t)bk * HH * COLS;

    auto fill = [&](int s, int k0) {
        float* Ah = sm + s * RBUF;
        float* Al = Ah + 4352;
        float* Bh = Al + 4352;
        float* Bl = Bh + 2304;
        const int p = tid - 128;
        for (int i = p; i < 1024; i += 128) {           // H: 64 rows x 16 float4
            int row = i >> 4, q = i & 15;
            *(float4*)&Ah[row * RSA + q * 4] =
                *(const float4*)&g_Hhi[row * HH + k0 + q * 4];
            *(float4*)&Al[row * RSA + q * 4] =
                *(const float4*)&g_Hlo[row * HH + k0 + q * 4];
        }
        for (int i = p; i < 512; i += 128) {            // W: 64 rows x 8 float4
            int row = i >> 3, q = i & 7;
            *(float4*)&Bh[row * RSB + q * 4] =
                *(const float4*)&Wh[(size_t)(k0 + row) * COLS + q * 4];
            *(float4*)&Bl[row * RSB + q * 4] =
                *(const float4*)&Wl[(size_t)(k0 + row) * COLS + q * 4];
        }
    };

    __syncthreads();

    for (int t = 0; t < TT; ++t) {
        float accA[4][4], accB[4][4];
#pragma unroll
        for (int i = 0; i < 4; ++i)
#pragma unroll
            for (int j = 0; j < 4; ++j) { accA[i][j] = 0.f; accB[i][j] = 0.f; }

        if (wid >= 4) fill(0, 0);
        __syncthreads();

        for (int c = 0; c < HH / RKC; ++c) {
            if (wid >= 4) {
                if (c + 1 < HH / RKC) fill((c + 1) & 1, (c + 1) * RKC);
            } else {
                const float* Ah = sm + (c & 1) * RBUF;
                const float* Al = Ah + 4352;
                const float* Bh = Al + 4352;
                const float* Bl = Bh + 2304;
                const int r0 = wid * 16 + g;
#pragma unroll
                for (int kk8 = 0; kk8 < 8; ++kk8) {
                    const int k = kk8 * 8;
                    float ah0 = Ah[r0 * RSA + k + t4];
                    float ah1 = Ah[(r0 + 8) * RSA + k + t4];
                    float ah2 = Ah[r0 * RSA + k + t4 + 4];
                    float ah3 = Ah[(r0 + 8) * RSA + k + t4 + 4];
                    float al0 = Al[r0 * RSA + k + t4];
                    float al1 = Al[(r0 + 8) * RSA + k + t4];
                    float al2 = Al[r0 * RSA + k + t4 + 4];
                    float al3 = Al[(r0 + 8) * RSA + k + t4 + 4];
#pragma unroll
                    for (int nt = 0; nt < 4; ++nt) {
                        float bh0 = Bh[(k + t4) * RSB + nt * 8 + g];
                        float bh1 = Bh[(k + t4 + 4) * RSB + nt * 8 + g];
                        float bl0 = Bl[(k + t4) * RSB + nt * 8 + g];
                        float bl1 = Bl[(k + t4 + 4) * RSB + nt * 8 + g];
                        mma8(accA[nt], ah0, ah1, ah2, ah3, bh0, bh1);
                        mma8(accB[nt], ah0, ah1, ah2, ah3, bl0, bl1);
                        mma8(accB[nt], al0, al1, al2, al3, bh0, bh1);
                    }
                }
            }
            __syncthreads();
        }

        // Pointwise LSTM cell: all 4 gates for (row, h) live in this thread's frags.
        if (wid < 4) {
            const int r0 = wid * 16 + g;
            const float* xg = g_XG + ((size_t)t * NBLK + bk) * BB * COLS;
#pragma unroll
            for (int j = 0; j < 2; ++j) {
                const int row = r0 + 8 * j;
#pragma unroll
                for (int i = 0; i < 2; ++i) {
                    const int h  = 2 * t4 + i;
                    const int ci = 2 * j + i;
                    float gi = accA[0][ci] + accB[0][ci] + xg[row * COLS + h];
                    float gf = accA[1][ci] + accB[1][ci] + xg[row * COLS + 8 + h];
                    float go = accA[2][ci] + accB[2][ci] + xg[row * COLS + 16 + h];
                    float gg = accA[3][ci] + accB[3][ci] + xg[row * COLS + 24 + h];
                    float I  = 1.f / (1.f + __expf(-gi));
                    float F  = 1.f / (1.f + __expf(-gf));
                    float O  = 1.f / (1.f + __expf(-go));
                    float Cn = F * Cs[row * 8 + h] + I * tanhf(gg);
                    float Hn = O * tanhf(Cn);
                    Cs[row * 8 + h] = Cn;
                    const int col = bk * CPB + h;
                    out[((size_t)t * BB + row) * HH + col] = Hn;
                    float hh = tf32_rd(Hn);
                    g_Hhi[row * HH + col] = hh;
                    g_Hlo[row * HH + col] = tf32_rd(Hn - hh);
                    if (t == TT - 1 && out_size >= TT * BB * HH + 2 * BB * HH) {
                        out[(size_t)TT * BB * HH + row * HH + col] = Hn;
                        out[(size_t)TT * BB * HH + BB * HH + row * HH + col] = Cn;
                    }
                }
            }
        }

        // grid barrier (monotonic counter; 128 CTAs co-resident)
        __syncthreads();
        if (tid == 0) {
            __threadfence();
            atomicAdd(&g_bar, 1u);
            const unsigned target = (unsigned)(t + 1) * NBLK;
            while (*((volatile unsigned*)&g_bar) < target) { }
            __threadfence();
        }
        __syncthreads();
    }
}

// ---------------------------------------------------------------------------
extern "C" void kernel_launch(void* const* d_in, const int* in_sizes, int n_in,
                              void* d_out, int out_size) {
    const float* inputs = (const float*)d_in[0];
    const float* H0     = (const float*)d_in[1];
    const float* C0     = (const float*)d_in[2];
    const float* W_xi   = (const float*)d_in[3];
    const float* W_xf   = (const float*)d_in[4];
    const float* W_xo   = (const float*)d_in[5];
    const float* W_xc   = (const float*)d_in[6];
    const float* W_hi   = (const float*)d_in[7];
    const float* W_hf   = (const float*)d_in[8];
    const float* W_ho   = (const float*)d_in[9];
    const float* W_hc   = (const float*)d_in[10];
    const float* b_i    = (const float*)d_in[11];
    const float* b_f    = (const float*)d_in[12];
    const float* b_o    = (const float*)d_in[13];
    const float* b_c    = (const float*)d_in[14];
    float* out = (float*)d_out;

    const int xg_smem  = 2 * XBUF * sizeof(float);               // 104448 B
    const int rec_smem = (2 * RBUF + BB * CPB) * sizeof(float);  // 108544 B
    cudaFuncSetAttribute(xgemm3_kernel, cudaFuncAttributeMaxDynamicSharedMemorySize, xg_smem);
    cudaFuncSetAttribute(rec3_kernel,  cudaFuncAttributeMaxDynamicSharedMemorySize, rec_smem);

    init_kernel<<<64, 1024>>>(H0);
    pack_wh_kernel<<<(NBLK * HH * COLS) / 1024, 1024>>>(W_hi, W_hf, W_ho, W_hc);

    dim3 ggrid(32, 512);   // n-tiles x t
    xgemm3_kernel<<<ggrid, 256, xg_smem>>>(inputs, W_xi, W_xf, W_xo, W_xc,
                                           b_i, b_f, b_o, b_c);

    rec3_kernel<<<NBLK, 256, rec_smem>>>(C0, out, out_size);
}